// round 10
// baseline (speedup 1.0000x reference)
#include <cuda_runtime.h>
#include <cuda_fp16.h>

#define DD 64
#define NMAX 100000
#define EMAX 1600000
#define NB_SCAN 240

// -------- scratch (static device globals; zero-initialized at load) --------
__device__ __half g_th[NMAX * DD];     // t = h @ W (half)
__device__ __half g_hh[NMAX * DD];     // h after agg (half)
__device__ int    g_deg[NMAX];         // zero at entry; reset by k_scatter each call
__device__ int    g_offs[NMAX + 1];
__device__ int    g_cursor[NMAX];
__device__ int    g_srcs[EMAX];
__device__ float  g_invdeg[NMAX];
__device__ int    g_bsum[NB_SCAN];

// -------- one-time stream/event setup (host-side only) --------
struct HxStreams {
    cudaStream_t s2;
    cudaEvent_t evFork, evJoin;
    HxStreams() {
        cudaStreamCreateWithFlags(&s2, cudaStreamNonBlocking);
        cudaEventCreateWithFlags(&evFork, cudaEventDisableTiming);
        cudaEventCreateWithFlags(&evJoin, cudaEventDisableTiming);
    }
};
static HxStreams g_hx;

#define MMA16816(c0,c1,c2,c3,a0,a1,a2,a3,b0,b1) \
    asm volatile("mma.sync.aligned.m16n8k16.row.col.f32.f16.f16.f32 " \
        "{%0,%1,%2,%3}, {%4,%5,%6,%7}, {%8,%9}, {%0,%1,%2,%3};" \
        : "+f"(c0), "+f"(c1), "+f"(c2), "+f"(c3) \
        : "r"(a0), "r"(a1), "r"(a2), "r"(a3), "r"(b0), "r"(b1))

// -------- degree count: 8 edges/thread, batched atomics --------
__global__ void k_deg(const int* __restrict__ dst, int e) {
    int i = blockIdx.x * blockDim.x + threadIdx.x;
    int base = i * 8;
    if (base + 8 <= e) {
        int4 d0 = *(const int4*)(dst + base);
        int4 d1 = *(const int4*)(dst + base + 4);
        atomicAdd(&g_deg[d0.x], 1); atomicAdd(&g_deg[d0.y], 1);
        atomicAdd(&g_deg[d0.z], 1); atomicAdd(&g_deg[d0.w], 1);
        atomicAdd(&g_deg[d1.x], 1); atomicAdd(&g_deg[d1.y], 1);
        atomicAdd(&g_deg[d1.z], 1); atomicAdd(&g_deg[d1.w], 1);
    } else {
        for (int j = base; j < e; ++j) atomicAdd(&g_deg[dst[j]], 1);
    }
}

// -------- scan phase A: per-block sums --------
__global__ void k_scan_a(int n) {
    __shared__ int s[256];
    int b = blockIdx.x;
    int ch = (n + NB_SCAN - 1) / NB_SCAN;
    int lo = b * ch, hi = min(n, lo + ch);
    int t = threadIdx.x;
    int acc = 0;
    for (int i = lo + t; i < hi; i += 256) acc += g_deg[i];
    s[t] = acc;
    __syncthreads();
    for (int off = 128; off > 0; off >>= 1) {
        if (t < off) s[t] += s[t + off];
        __syncthreads();
    }
    if (t == 0) g_bsum[b] = s[0];
}

// -------- scan phase C: 512 threads, single-tile warp-shuffle scan --------
__global__ void k_scan_c(int n, int e) {
    __shared__ int wsum[16];
    __shared__ int sCarry;
    int b = blockIdx.x;
    int t = threadIdx.x;
    int lane = t & 31, wid = t >> 5;
    if (b == 0 && t == 0) g_offs[n] = e;

    if (wid == 0) {
        int acc = 0;
        for (int i = lane; i < b; i += 32) acc += g_bsum[i];
        #pragma unroll
        for (int off = 16; off > 0; off >>= 1)
            acc += __shfl_down_sync(0xFFFFFFFFu, acc, off);
        if (lane == 0) sCarry = acc;
    }
    __syncthreads();
    int carry = sCarry;

    int ch = (n + NB_SCAN - 1) / NB_SCAN;
    int lo = b * ch, hi = min(n, lo + ch);
    for (int base = lo; base < hi; base += 512) {
        int idx = base + t;
        int v = (idx < hi) ? g_deg[idx] : 0;
        int sc = v;
        #pragma unroll
        for (int off = 1; off < 32; off <<= 1) {
            int x = __shfl_up_sync(0xFFFFFFFFu, sc, off);
            if (lane >= off) sc += x;
        }
        if (lane == 31) wsum[wid] = sc;
        __syncthreads();
        int woff = 0;
        #pragma unroll
        for (int w = 0; w < 16; ++w) if (w < wid) woff += wsum[w];
        int total = woff;
        #pragma unroll
        for (int w = 0; w < 16; ++w) if (w >= wid) total += wsum[w];
        if (idx < hi) {
            int exc = carry + woff + sc - v;
            g_offs[idx]   = exc;
            g_cursor[idx] = exc;
            g_invdeg[idx] = 1.0f / (float)(v > 0 ? v : 1);
        }
        carry += total;
        __syncthreads();
    }
}

// -------- scatter edges into CSR: 8 edges/thread; resets g_deg --------
__global__ void k_scatter(const int* __restrict__ src, const int* __restrict__ dst,
                          int e, int n) {
    int i = blockIdx.x * blockDim.x + threadIdx.x;
    int base = i * 8;
    if (base + 8 <= e) {
        int4 s0 = *(const int4*)(src + base);
        int4 s1 = *(const int4*)(src + base + 4);
        int4 d0 = *(const int4*)(dst + base);
        int4 d1 = *(const int4*)(dst + base + 4);
        int p[8];
        p[0] = atomicAdd(&g_cursor[d0.x], 1);
        p[1] = atomicAdd(&g_cursor[d0.y], 1);
        p[2] = atomicAdd(&g_cursor[d0.z], 1);
        p[3] = atomicAdd(&g_cursor[d0.w], 1);
        p[4] = atomicAdd(&g_cursor[d1.x], 1);
        p[5] = atomicAdd(&g_cursor[d1.y], 1);
        p[6] = atomicAdd(&g_cursor[d1.z], 1);
        p[7] = atomicAdd(&g_cursor[d1.w], 1);
        g_srcs[p[0]] = s0.x; g_srcs[p[1]] = s0.y;
        g_srcs[p[2]] = s0.z; g_srcs[p[3]] = s0.w;
        g_srcs[p[4]] = s1.x; g_srcs[p[5]] = s1.y;
        g_srcs[p[6]] = s1.z; g_srcs[p[7]] = s1.w;
    } else {
        for (int j = base; j < e; ++j)
            g_srcs[atomicAdd(&g_cursor[dst[j]], 1)] = src[j];
    }
    if (i < n) g_deg[i] = 0;
}

// -------- tensor-core GEMM (layer 1): t1(half) = emb[tok] @ W1 --------
__global__ void k_gemm_mma(const int* __restrict__ tok, const float* __restrict__ emb,
                           const float* __restrict__ W, __half* __restrict__ tout, int n) {
    __shared__ __half sA[64 * 72];
    __shared__ __half sW[64 * 72];     // transposed: sW[n*72 + k]
    int t = threadIdx.x;               // 128
    int row0 = blockIdx.x * 64;

    #pragma unroll
    for (int it = 0; it < 8; ++it) {
        int flat = t + it * 128;       // float4 over 64x16
        int k  = flat >> 4;
        int n4 = (flat & 15) * 4;
        float4 w = ((const float4*)W)[flat];
        sW[(n4 + 0) * 72 + k] = __float2half(w.x);
        sW[(n4 + 1) * 72 + k] = __float2half(w.y);
        sW[(n4 + 2) * 72 + k] = __float2half(w.z);
        sW[(n4 + 3) * 72 + k] = __float2half(w.w);
    }
    #pragma unroll
    for (int it = 0; it < 8; ++it) {
        int flat = t + it * 128;
        int r = flat >> 4, c4 = flat & 15;
        int gr = row0 + r;
        float4 v = make_float4(0.f, 0.f, 0.f, 0.f);
        if (gr < n) v = ((const float4*)emb)[tok[gr] * 16 + c4];
        *(__half2*)&sA[r * 72 + c4 * 4]     = __floats2half2_rn(v.x, v.y);
        *(__half2*)&sA[r * 72 + c4 * 4 + 2] = __floats2half2_rn(v.z, v.w);
    }
    __syncthreads();

    int w = t >> 5, lane = t & 31;
    int g = lane >> 2, t2 = lane & 3;
    int R = w * 16;
    float acc[8][4];
    #pragma unroll
    for (int i = 0; i < 8; ++i)
        #pragma unroll
        for (int j = 0; j < 4; ++j) acc[i][j] = 0.f;

    #pragma unroll
    for (int kt = 0; kt < 4; ++kt) {
        int c = kt * 16 + t2 * 2;
        unsigned a0 = *(unsigned*)&sA[(R + g)     * 72 + c];
        unsigned a1 = *(unsigned*)&sA[(R + g + 8) * 72 + c];
        unsigned a2 = *(unsigned*)&sA[(R + g)     * 72 + c + 8];
        unsigned a3 = *(unsigned*)&sA[(R + g + 8) * 72 + c + 8];
        #pragma unroll
        for (int nt = 0; nt < 8; ++nt) {
            unsigned b0 = *(unsigned*)&sW[(nt * 8 + g) * 72 + c];
            unsigned b1 = *(unsigned*)&sW[(nt * 8 + g) * 72 + c + 8];
            MMA16816(acc[nt][0], acc[nt][1], acc[nt][2], acc[nt][3],
                     a0, a1, a2, a3, b0, b1);
        }
    }

    int r1 = row0 + R + g;
    int r2 = r1 + 8;
    #pragma unroll
    for (int nt = 0; nt < 8; ++nt) {
        int col = nt * 8 + t2 * 2;
        if (r1 < n) *(__half2*)&tout[r1 * 64 + col] = __floats2half2_rn(acc[nt][0], acc[nt][1]);
        if (r2 < n) *(__half2*)&tout[r2 * 64 + col] = __floats2half2_rn(acc[nt][2], acc[nt][3]);
    }
}

// -------- FUSED agg-1 + GEMM-2: t2 = relu(agg(t1)*invdeg + b1) @ W2 --------
// 512 threads = 64 nodes x 8; agg into smem A-tile, then 16 warps x (16x16) mma.
__global__ void k_agg_gemm(const __half* __restrict__ tin, const float* __restrict__ b,
                           const float* __restrict__ W, __half* __restrict__ tout, int n) {
    __shared__ __half sA[64 * 72];
    __shared__ __half sW[64 * 72];     // transposed
    int t = threadIdx.x;               // 512
    int row0 = blockIdx.x * 64;

    // W (float [k][n]) -> sW[n][k] half : 1024 float4 slots, 2 iters
    #pragma unroll
    for (int it = 0; it < 2; ++it) {
        int flat = t + it * 512;
        int k  = flat >> 4;
        int n4 = (flat & 15) * 4;
        float4 w = ((const float4*)W)[flat];
        sW[(n4 + 0) * 72 + k] = __float2half(w.x);
        sW[(n4 + 1) * 72 + k] = __float2half(w.y);
        sW[(n4 + 2) * 72 + k] = __float2half(w.z);
        sW[(n4 + 3) * 72 + k] = __float2half(w.w);
    }

    // agg: this thread owns node row r, feature slice d8 (8 halves)
    int r = t >> 3;
    int node = row0 + r;
    int d8 = t & 7;
    const uint4* t4 = (const uint4*)tin;
    float2 a0 = make_float2(0.f, 0.f), a1 = a0, a2 = a0, a3 = a0;
    if (node < n) {
        int s0 = g_offs[node], s1 = g_offs[node + 1];
        int e = s0;
        for (; e + 8 <= s1; e += 8) {
            uint4 v[8];
            #pragma unroll
            for (int q = 0; q < 8; ++q) {
                int sn = g_srcs[e + q];
                v[q] = __ldcg(&t4[sn * 8 + d8]);
            }
            #pragma unroll
            for (int q = 0; q < 8; ++q) {
                float2 f0 = __half22float2(*(__half2*)&v[q].x);
                float2 f1 = __half22float2(*(__half2*)&v[q].y);
                float2 f2 = __half22float2(*(__half2*)&v[q].z);
                float2 f3 = __half22float2(*(__half2*)&v[q].w);
                a0.x += f0.x; a0.y += f0.y;
                a1.x += f1.x; a1.y += f1.y;
                a2.x += f2.x; a2.y += f2.y;
                a3.x += f3.x; a3.y += f3.y;
            }
        }
        for (; e < s1; ++e) {
            uint4 v = __ldcg(&t4[g_srcs[e] * 8 + d8]);
            float2 f0 = __half22float2(*(__half2*)&v.x);
            float2 f1 = __half22float2(*(__half2*)&v.y);
            float2 f2 = __half22float2(*(__half2*)&v.z);
            float2 f3 = __half22float2(*(__half2*)&v.w);
            a0.x += f0.x; a0.y += f0.y;
            a1.x += f1.x; a1.y += f1.y;
            a2.x += f2.x; a2.y += f2.y;
            a3.x += f3.x; a3.y += f3.y;
        }
    }
    __half2 p0, p1, p2, p3;
    if (node < n) {
        float id = g_invdeg[node];
        float4 b0 = ((const float4*)b)[d8 * 2];
        float4 b1 = ((const float4*)b)[d8 * 2 + 1];
        p0 = __floats2half2_rn(fmaxf(a0.x * id + b0.x, 0.f), fmaxf(a0.y * id + b0.y, 0.f));
        p1 = __floats2half2_rn(fmaxf(a1.x * id + b0.z, 0.f), fmaxf(a1.y * id + b0.w, 0.f));
        p2 = __floats2half2_rn(fmaxf(a2.x * id + b1.x, 0.f), fmaxf(a2.y * id + b1.y, 0.f));
        p3 = __floats2half2_rn(fmaxf(a3.x * id + b1.z, 0.f), fmaxf(a3.y * id + b1.w, 0.f));
    } else {
        p0 = p1 = p2 = p3 = __floats2half2_rn(0.f, 0.f);
    }
    *(uint2*)&sA[r * 72 + d8 * 8]     = make_uint2(*(unsigned*)&p0, *(unsigned*)&p1);
    *(uint2*)&sA[r * 72 + d8 * 8 + 4] = make_uint2(*(unsigned*)&p2, *(unsigned*)&p3);
    __syncthreads();

    // GEMM: 16 warps; warp w -> rows [(w>>2)*16, +16), cols [(w&3)*16, +16)
    int w = t >> 5, lane = t & 31;
    int g = lane >> 2, t2 = lane & 3;
    int R  = (w >> 2) * 16;
    int CG = (w & 3) * 16;
    float acc[2][4];
    #pragma unroll
    for (int i = 0; i < 2; ++i)
        #pragma unroll
        for (int j = 0; j < 4; ++j) acc[i][j] = 0.f;

    #pragma unroll
    for (int kt = 0; kt < 4; ++kt) {
        int c = kt * 16 + t2 * 2;
        unsigned a0u = *(unsigned*)&sA[(R + g)     * 72 + c];
        unsigned a1u = *(unsigned*)&sA[(R + g + 8) * 72 + c];
        unsigned a2u = *(unsigned*)&sA[(R + g)     * 72 + c + 8];
        unsigned a3u = *(unsigned*)&sA[(R + g + 8) * 72 + c + 8];
        #pragma unroll
        for (int nt = 0; nt < 2; ++nt) {
            unsigned b0 = *(unsigned*)&sW[(CG + nt * 8 + g) * 72 + c];
            unsigned b1 = *(unsigned*)&sW[(CG + nt * 8 + g) * 72 + c + 8];
            MMA16816(acc[nt][0], acc[nt][1], acc[nt][2], acc[nt][3],
                     a0u, a1u, a2u, a3u, b0, b1);
        }
    }

    int r1 = row0 + R + g;
    int r2 = r1 + 8;
    #pragma unroll
    for (int nt = 0; nt < 2; ++nt) {
        int col = CG + nt * 8 + t2 * 2;
        if (r1 < n) *(__half2*)&tout[r1 * 64 + col] = __floats2half2_rn(acc[nt][0], acc[nt][1]);
        if (r2 < n) *(__half2*)&tout[r2 * 64 + col] = __floats2half2_rn(acc[nt][2], acc[nt][3]);
    }
}

// -------- aggregate (layer 2): hout(half) = relu(invdeg * sum t[src] + b) --------
__global__ void k_agg(const __half* __restrict__ tin, const float* __restrict__ b,
                      __half* __restrict__ hout, int n) {
    int node = blockIdx.x * 32 + (threadIdx.x >> 3);
    int d8 = threadIdx.x & 7;
    if (node >= n) return;
    int s0 = g_offs[node], s1 = g_offs[node + 1];
    const uint4* t4 = (const uint4*)tin;

    float2 a0 = make_float2(0.f, 0.f), a1 = a0, a2 = a0, a3 = a0;
    int e = s0;
    for (; e + 8 <= s1; e += 8) {
        uint4 v[8];
        #pragma unroll
        for (int q = 0; q < 8; ++q) {
            int sn = g_srcs[e + q];
            v[q] = __ldcg(&t4[sn * 8 + d8]);
        }
        #pragma unroll
        for (int q = 0; q < 8; ++q) {
            float2 f0 = __half22float2(*(__half2*)&v[q].x);
            float2 f1 = __half22float2(*(__half2*)&v[q].y);
            float2 f2 = __half22float2(*(__half2*)&v[q].z);
            float2 f3 = __half22float2(*(__half2*)&v[q].w);
            a0.x += f0.x; a0.y += f0.y;
            a1.x += f1.x; a1.y += f1.y;
            a2.x += f2.x; a2.y += f2.y;
            a3.x += f3.x; a3.y += f3.y;
        }
    }
    for (; e < s1; ++e) {
        uint4 v = __ldcg(&t4[g_srcs[e] * 8 + d8]);
        float2 f0 = __half22float2(*(__half2*)&v.x);
        float2 f1 = __half22float2(*(__half2*)&v.y);
        float2 f2 = __half22float2(*(__half2*)&v.z);
        float2 f3 = __half22float2(*(__half2*)&v.w);
        a0.x += f0.x; a0.y += f0.y;
        a1.x += f1.x; a1.y += f1.y;
        a2.x += f2.x; a2.y += f2.y;
        a3.x += f3.x; a3.y += f3.y;
    }

    float id = g_invdeg[node];
    float4 b0 = ((const float4*)b)[d8 * 2];
    float4 b1 = ((const float4*)b)[d8 * 2 + 1];
    __half2 p0 = __floats2half2_rn(fmaxf(a0.x * id + b0.x, 0.f), fmaxf(a0.y * id + b0.y, 0.f));
    __half2 p1 = __floats2half2_rn(fmaxf(a1.x * id + b0.z, 0.f), fmaxf(a1.y * id + b0.w, 0.f));
    __half2 p2 = __floats2half2_rn(fmaxf(a2.x * id + b1.x, 0.f), fmaxf(a2.y * id + b1.y, 0.f));
    __half2 p3 = __floats2half2_rn(fmaxf(a3.x * id + b1.z, 0.f), fmaxf(a3.y * id + b1.w, 0.f));
    uint4 pk;
    pk.x = *(unsigned*)&p0; pk.y = *(unsigned*)&p1;
    pk.z = *(unsigned*)&p2; pk.w = *(unsigned*)&p3;
    ((uint4*)hout)[node * 8 + d8] = pk;
}

// -------- fused mean-pool + classifier: one block per graph --------
__global__ void k_poolclass(const __half* __restrict__ h, const int* __restrict__ gid,
                            const float* __restrict__ Wc, const float* __restrict__ bc,
                            float* __restrict__ out, int n, int C) {
    int g = blockIdx.x;
    __shared__ int sLo, sHi;
    if (threadIdx.x == 0) {
        int lo = 0, hi = n;
        while (lo < hi) { int m = (lo + hi) >> 1; if (gid[m] < g) lo = m + 1; else hi = m; }
        sLo = lo;
        int lo2 = lo, hi2 = n;
        while (lo2 < hi2) { int m = (lo2 + hi2) >> 1; if (gid[m] < g + 1) lo2 = m + 1; else hi2 = m; }
        sHi = lo2;
    }
    __syncthreads();
    int lo = sLo, hi = sHi;
    int d  = threadIdx.x & 63;
    int rg = threadIdx.x >> 6;               // 0..7 (512 threads)
    float acc = 0.f;
    for (int i = lo + rg; i < hi; i += 8) acc += __half2float(h[i * 64 + d]);
    __shared__ float sm[512];
    __shared__ float mean[64];
    sm[threadIdx.x] = acc;
    __syncthreads();
    if (threadIdx.x < 64) {
        float s = 0.f;
        #pragma unroll
        for (int k = 0; k < 8; ++k) s += sm[k * 64 + d];
        float cnt = (float)(hi - lo);
        mean[d] = s / fmaxf(cnt, 1.f);
    }
    __syncthreads();
    if ((int)threadIdx.x < C) {
        int c = threadIdx.x;
        float s = 0.f;
        #pragma unroll
        for (int dd = 0; dd < 64; ++dd) s += mean[dd] * Wc[dd * C + c];
        out[g * C + c] = s + bc[c];
    }
}

extern "C" void kernel_launch(void* const* d_in, const int* in_sizes, int n_in,
                              void* d_out, int out_size) {
    const int*   tokens   = (const int*)d_in[0];
    const int*   edge_src = (const int*)d_in[1];
    const int*   edge_dst = (const int*)d_in[2];
    const int*   graph_id = (const int*)d_in[3];
    const float* emb      = (const float*)d_in[4];
    const float* W1       = (const float*)d_in[5];
    const float* b1       = (const float*)d_in[6];
    const float* W2       = (const float*)d_in[7];
    const float* b2       = (const float*)d_in[8];
    const float* Wc       = (const float*)d_in[9];
    const float* bc       = (const float*)d_in[10];
    float* out = (float*)d_out;

    int N = in_sizes[0];
    int E = in_sizes[1];
    int C = in_sizes[10];
    int G = out_size / C;

    __half *tb, *hb;
    cudaGetSymbolAddress((void**)&tb, g_th);
    cudaGetSymbolAddress((void**)&hb, g_hh);

    int e8 = (E + 7) / 8;

    // Fork: GEMM-1 (fused embedding) on side stream, CSR build on main stream.
    cudaEventRecord(g_hx.evFork, 0);
    cudaStreamWaitEvent(g_hx.s2, g_hx.evFork, 0);
    k_gemm_mma<<<(N + 63) / 64, 128, 0, g_hx.s2>>>(tokens, emb, W1, tb, N);
    cudaEventRecord(g_hx.evJoin, g_hx.s2);

    // CSR build (main stream)
    k_deg    <<<(e8 + 255) / 256, 256>>>(edge_dst, E);
    k_scan_a <<<NB_SCAN, 256>>>(N);
    k_scan_c <<<NB_SCAN, 512>>>(N, E);
    k_scatter<<<(e8 + 255) / 256, 256>>>(edge_src, edge_dst, E, N);

    // Join, then fused agg-1 + GEMM-2 -> t2 (writes g_hh as t2 buffer)
    cudaStreamWaitEvent(0, g_hx.evJoin, 0);
    k_agg_gemm<<<(N + 63) / 64, 512>>>(tb, b1, W2, hb, N);

    // agg-2 -> h2 (reuse g_th as h2 buffer)
    k_agg<<<(N + 31) / 32, 256>>>(hb, b2, tb, N);

    // fused pool + classify
    k_poolclass<<<G, 512>>>(tb, graph_id, Wc, bc, out, N, C);
}

// round 11
// speedup vs baseline: 1.0079x; 1.0079x over previous
#include <cuda_runtime.h>
#include <cuda_fp16.h>

#define DD 64
#define NMAX 100000
#define EMAX 1600000
#define NB_SCAN 240

// -------- scratch (static device globals; zero-initialized at load) --------
__device__ __half g_th[NMAX * DD];     // t = h @ W (half)
__device__ __half g_hh[NMAX * DD];     // h after agg (half)
__device__ int    g_deg[NMAX];         // zero at entry; reset by k_scatter each call
__device__ int    g_offs[NMAX + 1];
__device__ int    g_cursor[NMAX];
__device__ int    g_srcs[EMAX];
__device__ float  g_invdeg[NMAX];
__device__ int    g_bsum[NB_SCAN];

// -------- one-time stream/event setup (host-side only) --------
struct HxStreams {
    cudaStream_t s2;
    cudaEvent_t evFork, evJoin;
    HxStreams() {
        cudaStreamCreateWithFlags(&s2, cudaStreamNonBlocking);
        cudaEventCreateWithFlags(&evFork, cudaEventDisableTiming);
        cudaEventCreateWithFlags(&evJoin, cudaEventDisableTiming);
    }
};
static HxStreams g_hx;

#define MMA16816(c0,c1,c2,c3,a0,a1,a2,a3,b0,b1) \
    asm volatile("mma.sync.aligned.m16n8k16.row.col.f32.f16.f16.f32 " \
        "{%0,%1,%2,%3}, {%4,%5,%6,%7}, {%8,%9}, {%0,%1,%2,%3};" \
        : "+f"(c0), "+f"(c1), "+f"(c2), "+f"(c3) \
        : "r"(a0), "r"(a1), "r"(a2), "r"(a3), "r"(b0), "r"(b1))

// -------- degree count: 8 edges/thread, batched atomics --------
__global__ void k_deg(const int* __restrict__ dst, int e) {
    int i = blockIdx.x * blockDim.x + threadIdx.x;
    int base = i * 8;
    if (base + 8 <= e) {
        int4 d0 = *(const int4*)(dst + base);
        int4 d1 = *(const int4*)(dst + base + 4);
        atomicAdd(&g_deg[d0.x], 1); atomicAdd(&g_deg[d0.y], 1);
        atomicAdd(&g_deg[d0.z], 1); atomicAdd(&g_deg[d0.w], 1);
        atomicAdd(&g_deg[d1.x], 1); atomicAdd(&g_deg[d1.y], 1);
        atomicAdd(&g_deg[d1.z], 1); atomicAdd(&g_deg[d1.w], 1);
    } else {
        for (int j = base; j < e; ++j) atomicAdd(&g_deg[dst[j]], 1);
    }
}

// -------- scan phase A: per-block sums --------
__global__ void k_scan_a(int n) {
    __shared__ int s[256];
    int b = blockIdx.x;
    int ch = (n + NB_SCAN - 1) / NB_SCAN;
    int lo = b * ch, hi = min(n, lo + ch);
    int t = threadIdx.x;
    int acc = 0;
    for (int i = lo + t; i < hi; i += 256) acc += g_deg[i];
    s[t] = acc;
    __syncthreads();
    for (int off = 128; off > 0; off >>= 1) {
        if (t < off) s[t] += s[t + off];
        __syncthreads();
    }
    if (t == 0) g_bsum[b] = s[0];
}

// -------- scan phase C: 512 threads, single-tile warp-shuffle scan --------
__global__ void k_scan_c(int n, int e) {
    __shared__ int wsum[16];
    __shared__ int sCarry;
    int b = blockIdx.x;
    int t = threadIdx.x;
    int lane = t & 31, wid = t >> 5;
    if (b == 0 && t == 0) g_offs[n] = e;

    if (wid == 0) {
        int acc = 0;
        for (int i = lane; i < b; i += 32) acc += g_bsum[i];
        #pragma unroll
        for (int off = 16; off > 0; off >>= 1)
            acc += __shfl_down_sync(0xFFFFFFFFu, acc, off);
        if (lane == 0) sCarry = acc;
    }
    __syncthreads();
    int carry = sCarry;

    int ch = (n + NB_SCAN - 1) / NB_SCAN;
    int lo = b * ch, hi = min(n, lo + ch);
    for (int base = lo; base < hi; base += 512) {
        int idx = base + t;
        int v = (idx < hi) ? g_deg[idx] : 0;
        int sc = v;
        #pragma unroll
        for (int off = 1; off < 32; off <<= 1) {
            int x = __shfl_up_sync(0xFFFFFFFFu, sc, off);
            if (lane >= off) sc += x;
        }
        if (lane == 31) wsum[wid] = sc;
        __syncthreads();
        int woff = 0;
        #pragma unroll
        for (int w = 0; w < 16; ++w) if (w < wid) woff += wsum[w];
        int total = woff;
        #pragma unroll
        for (int w = 0; w < 16; ++w) if (w >= wid) total += wsum[w];
        if (idx < hi) {
            int exc = carry + woff + sc - v;
            g_offs[idx]   = exc;
            g_cursor[idx] = exc;
            g_invdeg[idx] = 1.0f / (float)(v > 0 ? v : 1);
        }
        carry += total;
        __syncthreads();
    }
}

// -------- scatter edges into CSR: 8 edges/thread; resets g_deg --------
__global__ void k_scatter(const int* __restrict__ src, const int* __restrict__ dst,
                          int e, int n) {
    int i = blockIdx.x * blockDim.x + threadIdx.x;
    int base = i * 8;
    if (base + 8 <= e) {
        int4 s0 = *(const int4*)(src + base);
        int4 s1 = *(const int4*)(src + base + 4);
        int4 d0 = *(const int4*)(dst + base);
        int4 d1 = *(const int4*)(dst + base + 4);
        int p[8];
        p[0] = atomicAdd(&g_cursor[d0.x], 1);
        p[1] = atomicAdd(&g_cursor[d0.y], 1);
        p[2] = atomicAdd(&g_cursor[d0.z], 1);
        p[3] = atomicAdd(&g_cursor[d0.w], 1);
        p[4] = atomicAdd(&g_cursor[d1.x], 1);
        p[5] = atomicAdd(&g_cursor[d1.y], 1);
        p[6] = atomicAdd(&g_cursor[d1.z], 1);
        p[7] = atomicAdd(&g_cursor[d1.w], 1);
        g_srcs[p[0]] = s0.x; g_srcs[p[1]] = s0.y;
        g_srcs[p[2]] = s0.z; g_srcs[p[3]] = s0.w;
        g_srcs[p[4]] = s1.x; g_srcs[p[5]] = s1.y;
        g_srcs[p[6]] = s1.z; g_srcs[p[7]] = s1.w;
    } else {
        for (int j = base; j < e; ++j)
            g_srcs[atomicAdd(&g_cursor[dst[j]], 1)] = src[j];
    }
    if (i < n) g_deg[i] = 0;
}

// -------- tensor-core GEMM (layer 1): t1(half) = emb[tok] @ W1 --------
__global__ void k_gemm_mma(const int* __restrict__ tok, const float* __restrict__ emb,
                           const float* __restrict__ W, __half* __restrict__ tout, int n) {
    __shared__ __half sA[64 * 72];
    __shared__ __half sW[64 * 72];     // transposed: sW[n*72 + k]
    int t = threadIdx.x;               // 128
    int row0 = blockIdx.x * 64;

    #pragma unroll
    for (int it = 0; it < 8; ++it) {
        int flat = t + it * 128;       // float4 over 64x16
        int k  = flat >> 4;
        int n4 = (flat & 15) * 4;
        float4 w = ((const float4*)W)[flat];
        sW[(n4 + 0) * 72 + k] = __float2half(w.x);
        sW[(n4 + 1) * 72 + k] = __float2half(w.y);
        sW[(n4 + 2) * 72 + k] = __float2half(w.z);
        sW[(n4 + 3) * 72 + k] = __float2half(w.w);
    }
    #pragma unroll
    for (int it = 0; it < 8; ++it) {
        int flat = t + it * 128;
        int r = flat >> 4, c4 = flat & 15;
        int gr = row0 + r;
        float4 v = make_float4(0.f, 0.f, 0.f, 0.f);
        if (gr < n) v = ((const float4*)emb)[tok[gr] * 16 + c4];
        *(__half2*)&sA[r * 72 + c4 * 4]     = __floats2half2_rn(v.x, v.y);
        *(__half2*)&sA[r * 72 + c4 * 4 + 2] = __floats2half2_rn(v.z, v.w);
    }
    __syncthreads();

    int w = t >> 5, lane = t & 31;
    int g = lane >> 2, t2 = lane & 3;
    int R = w * 16;
    float acc[8][4];
    #pragma unroll
    for (int i = 0; i < 8; ++i)
        #pragma unroll
        for (int j = 0; j < 4; ++j) acc[i][j] = 0.f;

    #pragma unroll
    for (int kt = 0; kt < 4; ++kt) {
        int c = kt * 16 + t2 * 2;
        unsigned a0 = *(unsigned*)&sA[(R + g)     * 72 + c];
        unsigned a1 = *(unsigned*)&sA[(R + g + 8) * 72 + c];
        unsigned a2 = *(unsigned*)&sA[(R + g)     * 72 + c + 8];
        unsigned a3 = *(unsigned*)&sA[(R + g + 8) * 72 + c + 8];
        #pragma unroll
        for (int nt = 0; nt < 8; ++nt) {
            unsigned b0 = *(unsigned*)&sW[(nt * 8 + g) * 72 + c];
            unsigned b1 = *(unsigned*)&sW[(nt * 8 + g) * 72 + c + 8];
            MMA16816(acc[nt][0], acc[nt][1], acc[nt][2], acc[nt][3],
                     a0, a1, a2, a3, b0, b1);
        }
    }

    int r1 = row0 + R + g;
    int r2 = r1 + 8;
    #pragma unroll
    for (int nt = 0; nt < 8; ++nt) {
        int col = nt * 8 + t2 * 2;
        if (r1 < n) *(__half2*)&tout[r1 * 64 + col] = __floats2half2_rn(acc[nt][0], acc[nt][1]);
        if (r2 < n) *(__half2*)&tout[r2 * 64 + col] = __floats2half2_rn(acc[nt][2], acc[nt][3]);
    }
}

// -------- FUSED agg-1 + GEMM-2: t2 = relu(agg(t1)*invdeg + b1) @ W2 --------
// 512 threads = 64 nodes x 8; agg into smem A-tile, then 16 warps x (16x16) mma.
__global__ void k_agg_gemm(const __half* __restrict__ tin, const float* __restrict__ b,
                           const float* __restrict__ W, __half* __restrict__ tout, int n) {
    __shared__ __half sA[64 * 72];
    __shared__ __half sW[64 * 72];     // transposed
    int t = threadIdx.x;               // 512
    int row0 = blockIdx.x * 64;

    // W (float [k][n]) -> sW[n][k] half : 1024 float4 slots, 2 iters
    #pragma unroll
    for (int it = 0; it < 2; ++it) {
        int flat = t + it * 512;
        int k  = flat >> 4;
        int n4 = (flat & 15) * 4;
        float4 w = ((const float4*)W)[flat];
        sW[(n4 + 0) * 72 + k] = __float2half(w.x);
        sW[(n4 + 1) * 72 + k] = __float2half(w.y);
        sW[(n4 + 2) * 72 + k] = __float2half(w.z);
        sW[(n4 + 3) * 72 + k] = __float2half(w.w);
    }

    // agg: this thread owns node row r, feature slice d8 (8 halves)
    int r = t >> 3;
    int node = row0 + r;
    int d8 = t & 7;
    const uint4* t4 = (const uint4*)tin;
    float2 a0 = make_float2(0.f, 0.f), a1 = a0, a2 = a0, a3 = a0;
    if (node < n) {
        int s0 = g_offs[node], s1 = g_offs[node + 1];
        int e = s0;
        for (; e + 8 <= s1; e += 8) {
            uint4 v[8];
            #pragma unroll
            for (int q = 0; q < 8; ++q) {
                int sn = g_srcs[e + q];
                v[q] = __ldcg(&t4[sn * 8 + d8]);
            }
            #pragma unroll
            for (int q = 0; q < 8; ++q) {
                float2 f0 = __half22float2(*(__half2*)&v[q].x);
                float2 f1 = __half22float2(*(__half2*)&v[q].y);
                float2 f2 = __half22float2(*(__half2*)&v[q].z);
                float2 f3 = __half22float2(*(__half2*)&v[q].w);
                a0.x += f0.x; a0.y += f0.y;
                a1.x += f1.x; a1.y += f1.y;
                a2.x += f2.x; a2.y += f2.y;
                a3.x += f3.x; a3.y += f3.y;
            }
        }
        for (; e < s1; ++e) {
            uint4 v = __ldcg(&t4[g_srcs[e] * 8 + d8]);
            float2 f0 = __half22float2(*(__half2*)&v.x);
            float2 f1 = __half22float2(*(__half2*)&v.y);
            float2 f2 = __half22float2(*(__half2*)&v.z);
            float2 f3 = __half22float2(*(__half2*)&v.w);
            a0.x += f0.x; a0.y += f0.y;
            a1.x += f1.x; a1.y += f1.y;
            a2.x += f2.x; a2.y += f2.y;
            a3.x += f3.x; a3.y += f3.y;
        }
    }
    __half2 p0, p1, p2, p3;
    if (node < n) {
        float id = g_invdeg[node];
        float4 b0 = ((const float4*)b)[d8 * 2];
        float4 b1 = ((const float4*)b)[d8 * 2 + 1];
        p0 = __floats2half2_rn(fmaxf(a0.x * id + b0.x, 0.f), fmaxf(a0.y * id + b0.y, 0.f));
        p1 = __floats2half2_rn(fmaxf(a1.x * id + b0.z, 0.f), fmaxf(a1.y * id + b0.w, 0.f));
        p2 = __floats2half2_rn(fmaxf(a2.x * id + b1.x, 0.f), fmaxf(a2.y * id + b1.y, 0.f));
        p3 = __floats2half2_rn(fmaxf(a3.x * id + b1.z, 0.f), fmaxf(a3.y * id + b1.w, 0.f));
    } else {
        p0 = p1 = p2 = p3 = __floats2half2_rn(0.f, 0.f);
    }
    *(uint2*)&sA[r * 72 + d8 * 8]     = make_uint2(*(unsigned*)&p0, *(unsigned*)&p1);
    *(uint2*)&sA[r * 72 + d8 * 8 + 4] = make_uint2(*(unsigned*)&p2, *(unsigned*)&p3);
    __syncthreads();

    // GEMM: 16 warps; warp w -> rows [(w>>2)*16, +16), cols [(w&3)*16, +16)
    int w = t >> 5, lane = t & 31;
    int g = lane >> 2, t2 = lane & 3;
    int R  = (w >> 2) * 16;
    int CG = (w & 3) * 16;
    float acc[2][4];
    #pragma unroll
    for (int i = 0; i < 2; ++i)
        #pragma unroll
        for (int j = 0; j < 4; ++j) acc[i][j] = 0.f;

    #pragma unroll
    for (int kt = 0; kt < 4; ++kt) {
        int c = kt * 16 + t2 * 2;
        unsigned a0u = *(unsigned*)&sA[(R + g)     * 72 + c];
        unsigned a1u = *(unsigned*)&sA[(R + g + 8) * 72 + c];
        unsigned a2u = *(unsigned*)&sA[(R + g)     * 72 + c + 8];
        unsigned a3u = *(unsigned*)&sA[(R + g + 8) * 72 + c + 8];
        #pragma unroll
        for (int nt = 0; nt < 2; ++nt) {
            unsigned b0 = *(unsigned*)&sW[(CG + nt * 8 + g) * 72 + c];
            unsigned b1 = *(unsigned*)&sW[(CG + nt * 8 + g) * 72 + c + 8];
            MMA16816(acc[nt][0], acc[nt][1], acc[nt][2], acc[nt][3],
                     a0u, a1u, a2u, a3u, b0, b1);
        }
    }

    int r1 = row0 + R + g;
    int r2 = r1 + 8;
    #pragma unroll
    for (int nt = 0; nt < 2; ++nt) {
        int col = CG + nt * 8 + t2 * 2;
        if (r1 < n) *(__half2*)&tout[r1 * 64 + col] = __floats2half2_rn(acc[nt][0], acc[nt][1]);
        if (r2 < n) *(__half2*)&tout[r2 * 64 + col] = __floats2half2_rn(acc[nt][2], acc[nt][3]);
    }
}

// -------- aggregate (layer 2): hout(half) = relu(invdeg * sum t[src] + b) --------
__global__ void k_agg(const __half* __restrict__ tin, const float* __restrict__ b,
                      __half* __restrict__ hout, int n) {
    int node = blockIdx.x * 32 + (threadIdx.x >> 3);
    int d8 = threadIdx.x & 7;
    if (node >= n) return;
    int s0 = g_offs[node], s1 = g_offs[node + 1];
    const uint4* t4 = (const uint4*)tin;

    float2 a0 = make_float2(0.f, 0.f), a1 = a0, a2 = a0, a3 = a0;
    int e = s0;
    for (; e + 8 <= s1; e += 8) {
        uint4 v[8];
        #pragma unroll
        for (int q = 0; q < 8; ++q) {
            int sn = g_srcs[e + q];
            v[q] = __ldcg(&t4[sn * 8 + d8]);
        }
        #pragma unroll
        for (int q = 0; q < 8; ++q) {
            float2 f0 = __half22float2(*(__half2*)&v[q].x);
            float2 f1 = __half22float2(*(__half2*)&v[q].y);
            float2 f2 = __half22float2(*(__half2*)&v[q].z);
            float2 f3 = __half22float2(*(__half2*)&v[q].w);
            a0.x += f0.x; a0.y += f0.y;
            a1.x += f1.x; a1.y += f1.y;
            a2.x += f2.x; a2.y += f2.y;
            a3.x += f3.x; a3.y += f3.y;
        }
    }
    for (; e < s1; ++e) {
        uint4 v = __ldcg(&t4[g_srcs[e] * 8 + d8]);
        float2 f0 = __half22float2(*(__half2*)&v.x);
        float2 f1 = __half22float2(*(__half2*)&v.y);
        float2 f2 = __half22float2(*(__half2*)&v.z);
        float2 f3 = __half22float2(*(__half2*)&v.w);
        a0.x += f0.x; a0.y += f0.y;
        a1.x += f1.x; a1.y += f1.y;
        a2.x += f2.x; a2.y += f2.y;
        a3.x += f3.x; a3.y += f3.y;
    }

    float id = g_invdeg[node];
    float4 b0 = ((const float4*)b)[d8 * 2];
    float4 b1 = ((const float4*)b)[d8 * 2 + 1];
    __half2 p0 = __floats2half2_rn(fmaxf(a0.x * id + b0.x, 0.f), fmaxf(a0.y * id + b0.y, 0.f));
    __half2 p1 = __floats2half2_rn(fmaxf(a1.x * id + b0.z, 0.f), fmaxf(a1.y * id + b0.w, 0.f));
    __half2 p2 = __floats2half2_rn(fmaxf(a2.x * id + b1.x, 0.f), fmaxf(a2.y * id + b1.y, 0.f));
    __half2 p3 = __floats2half2_rn(fmaxf(a3.x * id + b1.z, 0.f), fmaxf(a3.y * id + b1.w, 0.f));
    uint4 pk;
    pk.x = *(unsigned*)&p0; pk.y = *(unsigned*)&p1;
    pk.z = *(unsigned*)&p2; pk.w = *(unsigned*)&p3;
    ((uint4*)hout)[node * 8 + d8] = pk;
}

// -------- fused mean-pool + classifier: one block per graph --------
__global__ void k_poolclass(const __half* __restrict__ h, const int* __restrict__ gid,
                            const float* __restrict__ Wc, const float* __restrict__ bc,
                            float* __restrict__ out, int n, int C) {
    int g = blockIdx.x;
    __shared__ int sLo, sHi;
    if (threadIdx.x == 0) {
        int lo = 0, hi = n;
        while (lo < hi) { int m = (lo + hi) >> 1; if (gid[m] < g) lo = m + 1; else hi = m; }
        sLo = lo;
        int lo2 = lo, hi2 = n;
        while (lo2 < hi2) { int m = (lo2 + hi2) >> 1; if (gid[m] < g + 1) lo2 = m + 1; else hi2 = m; }
        sHi = lo2;
    }
    __syncthreads();
    int lo = sLo, hi = sHi;
    int d  = threadIdx.x & 63;
    int rg = threadIdx.x >> 6;               // 0..7 (512 threads)
    float acc = 0.f;
    for (int i = lo + rg; i < hi; i += 8) acc += __half2float(h[i * 64 + d]);
    __shared__ float sm[512];
    __shared__ float mean[64];
    sm[threadIdx.x] = acc;
    __syncthreads();
    if (threadIdx.x < 64) {
        float s = 0.f;
        #pragma unroll
        for (int k = 0; k < 8; ++k) s += sm[k * 64 + d];
        float cnt = (float)(hi - lo);
        mean[d] = s / fmaxf(cnt, 1.f);
    }
    __syncthreads();
    if ((int)threadIdx.x < C) {
        int c = threadIdx.x;
        float s = 0.f;
        #pragma unroll
        for (int dd = 0; dd < 64; ++dd) s += mean[dd] * Wc[dd * C + c];
        out[g * C + c] = s + bc[c];
    }
}

extern "C" void kernel_launch(void* const* d_in, const int* in_sizes, int n_in,
                              void* d_out, int out_size) {
    const int*   tokens   = (const int*)d_in[0];
    const int*   edge_src = (const int*)d_in[1];
    const int*   edge_dst = (const int*)d_in[2];
    const int*   graph_id = (const int*)d_in[3];
    const float* emb      = (const float*)d_in[4];
    const float* W1       = (const float*)d_in[5];
    const float* b1       = (const float*)d_in[6];
    const float* W2       = (const float*)d_in[7];
    const float* b2       = (const float*)d_in[8];
    const float* Wc       = (const float*)d_in[9];
    const float* bc       = (const float*)d_in[10];
    float* out = (float*)d_out;

    int N = in_sizes[0];
    int E = in_sizes[1];
    int C = in_sizes[10];
    int G = out_size / C;

    __half *tb, *hb;
    cudaGetSymbolAddress((void**)&tb, g_th);
    cudaGetSymbolAddress((void**)&hb, g_hh);

    int e8 = (E + 7) / 8;

    // Fork: GEMM-1 (fused embedding) on side stream, CSR build on main stream.
    cudaEventRecord(g_hx.evFork, 0);
    cudaStreamWaitEvent(g_hx.s2, g_hx.evFork, 0);
    k_gemm_mma<<<(N + 63) / 64, 128, 0, g_hx.s2>>>(tokens, emb, W1, tb, N);
    cudaEventRecord(g_hx.evJoin, g_hx.s2);

    // CSR build (main stream)
    k_deg    <<<(e8 + 255) / 256, 256>>>(edge_dst, E);
    k_scan_a <<<NB_SCAN, 256>>>(N);
    k_scan_c <<<NB_SCAN, 512>>>(N, E);
    k_scatter<<<(e8 + 255) / 256, 256>>>(edge_src, edge_dst, E, N);

    // Join, then fused agg-1 + GEMM-2 -> t2 (writes g_hh as t2 buffer)
    cudaStreamWaitEvent(0, g_hx.evJoin, 0);
    k_agg_gemm<<<(N + 63) / 64, 512>>>(tb, b1, W2, hb, N);

    // agg-2 -> h2 (reuse g_th as h2 buffer)
    k_agg<<<(N + 31) / 32, 256>>>(hb, b2, tb, N);

    // fused pool + classify
    k_poolclass<<<G, 512>>>(tb, graph_id, Wc, bc, out, N, C);
}